// round 16
// baseline (speedup 1.0000x reference)
#include <cuda_runtime.h>
#include <cstdint>

#define BATCH   262144
#define NIN     9
#define NHID    100
#define NPAIR   50
#define NOUT    2
#define TSTEPS  25
#define BETA    0.95f
#define NTHREADS 128

typedef unsigned long long u64;

__device__ __forceinline__ u64 pack2(float lo, float hi) {
    u64 r; asm("mov.b64 %0, {%1, %2};" : "=l"(r) : "f"(lo), "f"(hi)); return r;
}
__device__ __forceinline__ void unpack2(u64 v, float& lo, float& hi) {
    asm("mov.b64 {%0, %1}, %2;" : "=f"(lo), "=f"(hi) : "l"(v));
}
__device__ __forceinline__ u64 fma2(u64 a, u64 b, u64 c) {
    u64 d; asm("fma.rn.f32x2 %0, %1, %2, %3;" : "=l"(d) : "l"(a), "l"(b), "l"(c)); return d;
}
__device__ __forceinline__ u64 mul2(u64 a, u64 b) {
    u64 d; asm("mul.rn.f32x2 %0, %1, %2;" : "=l"(d) : "l"(a), "l"(b)); return d;
}
__device__ __forceinline__ u64 add2(u64 a, u64 b) {
    u64 d; asm("add.rn.f32x2 %0, %1, %2;" : "=l"(d) : "l"(a), "l"(b)); return d;
}
// Per-lane correctly-rounded subtract (== __fsub_rn per lane).
__device__ __forceinline__ u64 sub2(u64 a, u64 b) {
    u64 d; asm("sub.rn.f32x2 %0, %1, %2;" : "=l"(d) : "l"(a), "l"(b)); return d;
}
// Spike threshold on the ALU pipe (ISETP + SEL).
__device__ __forceinline__ float spike_alu(float m) {
    float s;
    asm("{\n\t"
        ".reg .pred p;\n\t"
        "setp.gt.s32 p, %1, 0x3F800000;\n\t"
        "selp.f32 %0, 0f3F800000, 0f00000000, p;\n\t"
        "}" : "=f"(s) : "r"(__float_as_int(m)));
    return s;
}
// Spike threshold on the FP pipe (single FSET): 1.0f if a > 1.0f else 0.0f.
// Identical boolean result to spike_alu — same compare, same {0,1} floats.
__device__ __forceinline__ float fset_gt1(float a) {
    float d; asm("set.gt.f32.f32 %0, %1, 0f3F800000;" : "=f"(d) : "f"(a)); return d;
}

__global__ __launch_bounds__(NTHREADS) void snn_kernel(
    const float* __restrict__ x,  const float* __restrict__ W1,
    const float* __restrict__ b1, const float* __restrict__ W2,
    const float* __restrict__ b2, float* __restrict__ out)
{
    // W1 interleaved unit-pairs as u64: sW1p[p*NIN+k] = (W1[2p][k], W1[2p+1][k])
    __shared__ u64 sW1p[NPAIR * NIN];
    __shared__ u64 sb1p[NPAIR];      // (b1[2p], b1[2p+1])
    // W2 interleaved OUTPUT-pairs: sw2i[h] = (W2[0][h], W2[1][h])
    __shared__ u64 sw2i[NHID];

    for (int i = threadIdx.x; i < NHID * NIN; i += blockDim.x) {
        int h = i / NIN, k = i % NIN;
        ((float*)&sW1p[(h >> 1) * NIN + k])[h & 1] = W1[i];
    }
    for (int i = threadIdx.x; i < NPAIR; i += blockDim.x) {
        ((float*)&sb1p[i])[0] = b1[2*i];
        ((float*)&sb1p[i])[1] = b1[2*i + 1];
    }
    for (int i = threadIdx.x; i < NHID; i += blockDim.x) {
        ((float*)&sw2i[i])[0] = W2[i];          // output 0 weight for unit i
        ((float*)&sw2i[i])[1] = W2[NHID + i];   // output 1 weight for unit i
    }
    __syncthreads();

    const int b = blockIdx.x * blockDim.x + threadIdx.x;  // one thread per element

    // Broadcast-packed input row, hoisted out of the j-loop.
    u64 xp[NIN];
    #pragma unroll
    for (int k = 0; k < NIN; k++) {
        const float xv = __ldg(&x[b * NIN + k]);
        xp[k] = pack2(xv, xv);
    }

    // Packed per-timestep cur2 partials: lane0 = out-0 chain, lane1 = out-1 chain.
    // Each lane is a serial ascending-h scalar fma chain (bit-matches reference).
    u64 accP[TSTEPS];
    #pragma unroll
    for (int t = 0; t < TSTEPS; t++) accP[t] = 0ull;

    const u64 BETA2 = pack2(BETA, BETA);

    // Main loop: FIVE pairs (10 hidden units) per iteration.
    // 10 iters x 5 pairs = all 50 pairs, no tail. h order ascending throughout.
    #pragma unroll 1
    for (int j = 0; j < 10; j++) {
        const int p0 = 5 * j;

        // Packed cur1 for 5 pairs: serial ascending-k fma chains, bias last.
        u64 cpA = 0ull, cpB = 0ull, cpC = 0ull, cpD = 0ull, cpE = 0ull;
        #pragma unroll
        for (int k = 0; k < NIN; k++) {
            const u64 xk = xp[k];
            cpA = fma2(xk, sW1p[(p0 + 0) * NIN + k], cpA);
            cpB = fma2(xk, sW1p[(p0 + 1) * NIN + k], cpB);
            cpC = fma2(xk, sW1p[(p0 + 2) * NIN + k], cpC);
            cpD = fma2(xk, sW1p[(p0 + 3) * NIN + k], cpD);
            cpE = fma2(xk, sW1p[(p0 + 4) * NIN + k], cpE);
        }
        cpA = add2(cpA, sb1p[p0 + 0]);
        cpB = add2(cpB, sb1p[p0 + 1]);
        cpC = add2(cpC, sb1p[p0 + 2]);
        cpD = add2(cpD, sb1p[p0 + 3]);
        cpE = add2(cpE, sb1p[p0 + 4]);

        const int h0 = 10 * j;
        const u64 w0 = sw2i[h0 + 0], w1 = sw2i[h0 + 1];
        const u64 w2 = sw2i[h0 + 2], w3 = sw2i[h0 + 3];
        const u64 w4 = sw2i[h0 + 4], w5 = sw2i[h0 + 5];
        const u64 w6 = sw2i[h0 + 6], w7 = sw2i[h0 + 7];
        const u64 w8 = sw2i[h0 + 8], w9 = sw2i[h0 + 9];

        // 25-step LIF for 10 hidden units: 5 independent (h_even, h_odd) chains.
        // reset(t) == spike(t-1). sub2(bc, r) == per-lane __fsub_rn.
        u64 mA = 0ull, rA = 0ull, mB = 0ull, rB = 0ull;
        u64 mC = 0ull, rC = 0ull, mD = 0ull, rD = 0ull;
        u64 mE = 0ull, rE = 0ull;
        #pragma unroll
        for (int t = 0; t < TSTEPS; t++) {
            const u64 bcA = add2(mul2(BETA2, mA), cpA);  // separate roundings
            const u64 bcB = add2(mul2(BETA2, mB), cpB);
            const u64 bcC = add2(mul2(BETA2, mC), cpC);
            const u64 bcD = add2(mul2(BETA2, mD), cpD);
            const u64 bcE = add2(mul2(BETA2, mE), cpE);
            mA = sub2(bcA, rA);
            mB = sub2(bcB, rB);
            mC = sub2(bcC, rC);
            mD = sub2(bcD, rD);
            mE = sub2(bcE, rE);

            float a0, a1, b0, b1v, c0, c1, d0, d1, e0, e1;
            unpack2(mA, a0, a1);
            unpack2(mB, b0, b1v);
            unpack2(mC, c0, c1);
            unpack2(mD, d0, d1);
            unpack2(mE, e0, e1);
            // Hybrid spike: lane-0 on the FP pipe (1 FSET), lane-1 on the ALU
            // pipe (ISETP+SEL). Identical {0,1} results; balances both pipes
            // while deleting one instruction per pair-step.
            const float sA0 = fset_gt1(a0),  sA1 = spike_alu(a1);
            const float sB0 = fset_gt1(b0),  sB1 = spike_alu(b1v);
            const float sC0 = fset_gt1(c0),  sC1 = spike_alu(c1);
            const float sD0 = fset_gt1(d0),  sD1 = spike_alu(d1);
            const float sE0 = fset_gt1(e0),  sE1 = spike_alu(e1);
            rA = pack2(sA0, sA1);
            rB = pack2(sB0, sB1);
            rC = pack2(sC0, sC1);
            rD = pack2(sD0, sD1);
            rE = pack2(sE0, sE1);

            // Packed acc (lane0 out0, lane1 out1), ascending-h serial order
            // units 10j .. 10j+9 — identical chain to the reference matmul.
            accP[t] = fma2(pack2(sA0, sA0), w0, accP[t]);
            accP[t] = fma2(pack2(sA1, sA1), w1, accP[t]);
            accP[t] = fma2(pack2(sB0, sB0), w2, accP[t]);
            accP[t] = fma2(pack2(sB1, sB1), w3, accP[t]);
            accP[t] = fma2(pack2(sC0, sC0), w4, accP[t]);
            accP[t] = fma2(pack2(sC1, sC1), w5, accP[t]);
            accP[t] = fma2(pack2(sD0, sD0), w6, accP[t]);
            accP[t] = fma2(pack2(sD1, sD1), w7, accP[t]);
            accP[t] = fma2(pack2(sE0, sE0), w8, accP[t]);
            accP[t] = fma2(pack2(sE1, sE1), w9, accP[t]);
        }
    }

    // Output layer recurrence + coalesced float2 stores.
    const float b20 = __ldg(&b2[0]);
    const float b21 = __ldg(&b2[1]);
    float m0 = 0.0f, m1 = 0.0f;
    float s0 = 0.0f, s1 = 0.0f;   // spike == next step's reset

    float2* pspk = (float2*)out + (unsigned)b;                            // spk2_rec
    float2* pmem = (float2*)out + ((unsigned)TSTEPS * BATCH + (unsigned)b); // mem2_rec

    #pragma unroll
    for (int t = 0; t < TSTEPS; t++) {
        float a0, a1; unpack2(accP[t], a0, a1);
        const float c0 = __fadd_rn(a0, b20);
        const float c1 = __fadd_rn(a1, b21);

        m0 = __fsub_rn(__fadd_rn(__fmul_rn(BETA, m0), c0), s0);
        s0 = fset_gt1(m0);

        m1 = __fsub_rn(__fadd_rn(__fmul_rn(BETA, m1), c1), s1);
        s1 = fset_gt1(m1);

        pspk[(unsigned)t * BATCH] = make_float2(s0, s1);
        pmem[(unsigned)t * BATCH] = make_float2(m0, m1);
    }
}

extern "C" void kernel_launch(void* const* d_in, const int* in_sizes, int n_in,
                              void* d_out, int out_size) {
    const float* x  = (const float*)d_in[0];
    const float* W1 = (const float*)d_in[1];
    const float* b1 = (const float*)d_in[2];
    const float* W2 = (const float*)d_in[3];
    const float* b2 = (const float*)d_in[4];
    float* out = (float*)d_out;

    snn_kernel<<<BATCH / NTHREADS, NTHREADS>>>(x, W1, b1, W2, b2, out);
}

// round 17
// speedup vs baseline: 1.0454x; 1.0454x over previous
#include <cuda_runtime.h>
#include <cstdint>

#define BATCH   262144
#define NIN     9
#define NHID    100
#define NPAIR   50
#define NOUT    2
#define TSTEPS  25
#define BETA    0.95f
#define NTHREADS 128

typedef unsigned long long u64;

__device__ __forceinline__ u64 pack2(float lo, float hi) {
    u64 r; asm("mov.b64 %0, {%1, %2};" : "=l"(r) : "f"(lo), "f"(hi)); return r;
}
__device__ __forceinline__ void unpack2(u64 v, float& lo, float& hi) {
    asm("mov.b64 {%0, %1}, %2;" : "=f"(lo), "=f"(hi) : "l"(v));
}
__device__ __forceinline__ u64 fma2(u64 a, u64 b, u64 c) {
    u64 d; asm("fma.rn.f32x2 %0, %1, %2, %3;" : "=l"(d) : "l"(a), "l"(b), "l"(c)); return d;
}
__device__ __forceinline__ u64 mul2(u64 a, u64 b) {
    u64 d; asm("mul.rn.f32x2 %0, %1, %2;" : "=l"(d) : "l"(a), "l"(b)); return d;
}
__device__ __forceinline__ u64 add2(u64 a, u64 b) {
    u64 d; asm("add.rn.f32x2 %0, %1, %2;" : "=l"(d) : "l"(a), "l"(b)); return d;
}
// Per-lane correctly-rounded subtract (== __fsub_rn per lane).
__device__ __forceinline__ u64 sub2(u64 a, u64 b) {
    u64 d; asm("sub.rn.f32x2 %0, %1, %2;" : "=l"(d) : "l"(a), "l"(b)); return d;
}
// Spike threshold on the ALU pipe (ISETP + SEL). Keeps the loop-carried
// spike/reset path entirely on one pipe (R16 lesson: cross-pipe hops on the
// r-chain cost more than the instruction they save).
__device__ __forceinline__ float spike_alu(float m) {
    float s;
    asm("{\n\t"
        ".reg .pred p;\n\t"
        "setp.gt.s32 p, %1, 0x3F800000;\n\t"
        "selp.f32 %0, 0f3F800000, 0f00000000, p;\n\t"
        "}" : "=f"(s) : "r"(__float_as_int(m)));
    return s;
}
// FSET for the tiny epilogue (not hot)
__device__ __forceinline__ float fset_gt1(float a) {
    float d; asm("set.gt.f32.f32 %0, %1, 0f3F800000;" : "=f"(d) : "f"(a)); return d;
}

__global__ __launch_bounds__(NTHREADS) void snn_kernel(
    const float* __restrict__ x,  const float* __restrict__ W1,
    const float* __restrict__ b1, const float* __restrict__ W2,
    const float* __restrict__ b2, float* __restrict__ out)
{
    // W1 interleaved unit-pairs as u64: sW1p[p*NIN+k] = (W1[2p][k], W1[2p+1][k])
    __shared__ u64 sW1p[NPAIR * NIN];
    __shared__ u64 sb1p[NPAIR];      // (b1[2p], b1[2p+1])
    // W2 interleaved OUTPUT-pairs: sw2i[h] = (W2[0][h], W2[1][h])
    __shared__ u64 sw2i[NHID];

    for (int i = threadIdx.x; i < NHID * NIN; i += blockDim.x) {
        int h = i / NIN, k = i % NIN;
        ((float*)&sW1p[(h >> 1) * NIN + k])[h & 1] = W1[i];
    }
    for (int i = threadIdx.x; i < NPAIR; i += blockDim.x) {
        ((float*)&sb1p[i])[0] = b1[2*i];
        ((float*)&sb1p[i])[1] = b1[2*i + 1];
    }
    for (int i = threadIdx.x; i < NHID; i += blockDim.x) {
        ((float*)&sw2i[i])[0] = W2[i];          // output 0 weight for unit i
        ((float*)&sw2i[i])[1] = W2[NHID + i];   // output 1 weight for unit i
    }
    __syncthreads();

    const int b = blockIdx.x * blockDim.x + threadIdx.x;  // one thread per element

    // Broadcast-packed input row, hoisted out of the j-loop.
    u64 xp[NIN];
    #pragma unroll
    for (int k = 0; k < NIN; k++) {
        const float xv = __ldg(&x[b * NIN + k]);
        xp[k] = pack2(xv, xv);
    }

    // Packed per-timestep cur2 partials: lane0 = out-0 chain, lane1 = out-1 chain.
    // Each lane is a serial ascending-h scalar fma chain (bit-matches reference).
    u64 accP[TSTEPS];
    #pragma unroll
    for (int t = 0; t < TSTEPS; t++) accP[t] = 0ull;

    const u64 BETA2 = pack2(BETA, BETA);

    // Main loop: FIVE pairs (10 hidden units) per iteration.
    // 10 iters x 5 pairs = all 50 pairs, no tail. h order ascending throughout.
    #pragma unroll 1
    for (int j = 0; j < 10; j++) {
        const int p0 = 5 * j;
        const int h0 = 10 * j;

        // Issue the W2-weight and bias loads FIRST: their 29-cyc LDS latency
        // is then covered by the 45-FMA2 cur1 block below instead of stalling
        // the t-loop head. (Scheduling-only change; arithmetic identical.)
        const u64 w0 = sw2i[h0 + 0], w1 = sw2i[h0 + 1];
        const u64 w2 = sw2i[h0 + 2], w3 = sw2i[h0 + 3];
        const u64 w4 = sw2i[h0 + 4], w5 = sw2i[h0 + 5];
        const u64 w6 = sw2i[h0 + 6], w7 = sw2i[h0 + 7];
        const u64 w8 = sw2i[h0 + 8], w9 = sw2i[h0 + 9];
        const u64 bbA = sb1p[p0 + 0], bbB = sb1p[p0 + 1], bbC = sb1p[p0 + 2];
        const u64 bbD = sb1p[p0 + 3], bbE = sb1p[p0 + 4];

        // Packed cur1 for 5 pairs: serial ascending-k fma chains, bias last.
        u64 cpA = 0ull, cpB = 0ull, cpC = 0ull, cpD = 0ull, cpE = 0ull;
        #pragma unroll
        for (int k = 0; k < NIN; k++) {
            const u64 xk = xp[k];
            cpA = fma2(xk, sW1p[(p0 + 0) * NIN + k], cpA);
            cpB = fma2(xk, sW1p[(p0 + 1) * NIN + k], cpB);
            cpC = fma2(xk, sW1p[(p0 + 2) * NIN + k], cpC);
            cpD = fma2(xk, sW1p[(p0 + 3) * NIN + k], cpD);
            cpE = fma2(xk, sW1p[(p0 + 4) * NIN + k], cpE);
        }
        cpA = add2(cpA, bbA);
        cpB = add2(cpB, bbB);
        cpC = add2(cpC, bbC);
        cpD = add2(cpD, bbD);
        cpE = add2(cpE, bbE);

        // 25-step LIF for 10 hidden units: 5 independent (h_even, h_odd) chains.
        // reset(t) == spike(t-1). sub2(bc, r) == per-lane __fsub_rn.
        u64 mA = 0ull, rA = 0ull, mB = 0ull, rB = 0ull;
        u64 mC = 0ull, rC = 0ull, mD = 0ull, rD = 0ull;
        u64 mE = 0ull, rE = 0ull;
        #pragma unroll
        for (int t = 0; t < TSTEPS; t++) {
            const u64 bcA = add2(mul2(BETA2, mA), cpA);  // separate roundings
            const u64 bcB = add2(mul2(BETA2, mB), cpB);
            const u64 bcC = add2(mul2(BETA2, mC), cpC);
            const u64 bcD = add2(mul2(BETA2, mD), cpD);
            const u64 bcE = add2(mul2(BETA2, mE), cpE);
            mA = sub2(bcA, rA);
            mB = sub2(bcB, rB);
            mC = sub2(bcC, rC);
            mD = sub2(bcD, rD);
            mE = sub2(bcE, rE);

            float a0, a1, b0, b1v, c0, c1, d0, d1, e0, e1;
            unpack2(mA, a0, a1);
            unpack2(mB, b0, b1v);
            unpack2(mC, c0, c1);
            unpack2(mD, d0, d1);
            unpack2(mE, e0, e1);
            const float sA0 = spike_alu(a0), sA1 = spike_alu(a1);
            const float sB0 = spike_alu(b0), sB1 = spike_alu(b1v);
            const float sC0 = spike_alu(c0), sC1 = spike_alu(c1);
            const float sD0 = spike_alu(d0), sD1 = spike_alu(d1);
            const float sE0 = spike_alu(e0), sE1 = spike_alu(e1);
            rA = pack2(sA0, sA1);
            rB = pack2(sB0, sB1);
            rC = pack2(sC0, sC1);
            rD = pack2(sD0, sD1);
            rE = pack2(sE0, sE1);

            // Packed acc (lane0 out0, lane1 out1), ascending-h serial order
            // units 10j .. 10j+9 — identical chain to the reference matmul.
            accP[t] = fma2(pack2(sA0, sA0), w0, accP[t]);
            accP[t] = fma2(pack2(sA1, sA1), w1, accP[t]);
            accP[t] = fma2(pack2(sB0, sB0), w2, accP[t]);
            accP[t] = fma2(pack2(sB1, sB1), w3, accP[t]);
            accP[t] = fma2(pack2(sC0, sC0), w4, accP[t]);
            accP[t] = fma2(pack2(sC1, sC1), w5, accP[t]);
            accP[t] = fma2(pack2(sD0, sD0), w6, accP[t]);
            accP[t] = fma2(pack2(sD1, sD1), w7, accP[t]);
            accP[t] = fma2(pack2(sE0, sE0), w8, accP[t]);
            accP[t] = fma2(pack2(sE1, sE1), w9, accP[t]);
        }
    }

    // Output layer recurrence + coalesced float2 stores.
    const float b20 = __ldg(&b2[0]);
    const float b21 = __ldg(&b2[1]);
    float m0 = 0.0f, m1 = 0.0f;
    float s0 = 0.0f, s1 = 0.0f;   // spike == next step's reset

    float2* pspk = (float2*)out + (unsigned)b;                            // spk2_rec
    float2* pmem = (float2*)out + ((unsigned)TSTEPS * BATCH + (unsigned)b); // mem2_rec

    #pragma unroll
    for (int t = 0; t < TSTEPS; t++) {
        float a0, a1; unpack2(accP[t], a0, a1);
        const float c0 = __fadd_rn(a0, b20);
        const float c1 = __fadd_rn(a1, b21);

        m0 = __fsub_rn(__fadd_rn(__fmul_rn(BETA, m0), c0), s0);
        s0 = fset_gt1(m0);

        m1 = __fsub_rn(__fadd_rn(__fmul_rn(BETA, m1), c1), s1);
        s1 = fset_gt1(m1);

        pspk[(unsigned)t * BATCH] = make_float2(s0, s1);
        pmem[(unsigned)t * BATCH] = make_float2(m0, m1);
    }
}

extern "C" void kernel_launch(void* const* d_in, const int* in_sizes, int n_in,
                              void* d_out, int out_size) {
    const float* x  = (const float*)d_in[0];
    const float* W1 = (const float*)d_in[1];
    const float* b1 = (const float*)d_in[2];
    const float* W2 = (const float*)d_in[3];
    const float* b2 = (const float*)d_in[4];
    float* out = (float*)d_out;

    snn_kernel<<<BATCH / NTHREADS, NTHREADS>>>(x, W1, b1, W2, b2, out);
}